// round 15
// baseline (speedup 1.0000x reference)
#include <cuda_runtime.h>

#define ALPHA_F 0.1f

constexpr int Bb  = 32;
constexpr int Tt  = 2048;
constexpr int DIN = 128;
constexpr int Hh  = 512;
constexpr int CHUNK = 128;
constexpr int NCH  = Tt / CHUNK;
constexpr int W    = 8;                   // timesteps per barrier window
constexpr int NW   = Tt / W;              // 256 windows

__device__ float g_xproj[(size_t)Bb * Tt * Hh];
__device__ int g_cnt[Bb][NCH];

#define PACK2(d, lo, hi)   asm("mov.b64 %0, {%1, %2};" : "=l"(d) : "f"(lo), "f"(hi))
#define UNPACK2(lo, hi, s) asm("mov.b64 {%0, %1}, %2;" : "=f"(lo), "=f"(hi) : "l"(s))
#define FMA2(d, a, b)      asm("fma.rn.f32x2 %0, %1, %2, %0;" : "+l"(d) : "l"(a), "l"(b))

__device__ __forceinline__ float tanh_fast(float x) {
    float y;
    asm("tanh.approx.f32 %0, %1;" : "=f"(y) : "f"(x));
    return y;
}

constexpr float FXSCALE = 1048576.0f;        // 2^20 (A sums / delta domain)
constexpr float FXINV   = 1.0f / 1048576.0f;
constexpr float CSCALE  = 16777216.0f;       // 2^24 (C sums)
constexpr float CINV    = 1.0f / 16777216.0f;
constexpr float MAGICF  = 12582912.0f;       // 1.5*2^23
constexpr unsigned MAGICU = 0x4B400000u;
constexpr unsigned BIAS_FIX = (unsigned)(127u * MAGICU);  // mod 2^32
constexpr float MCC = -MAGICF * CINV;        // exact -0.75

constexpr int BM = 128, BN = 128, BK = 32;

__global__ void zero_cnt_kernel() {
    int i = threadIdx.x;
    if (i < Bb * NCH) ((int*)g_cnt)[i] = 0;
}

__device__ __forceinline__ void wait_chunk(int b, int c) {
    volatile int* p = &g_cnt[b][c];
    if (*p < 4) {
        while (*p < 4) __nanosleep(64);
    }
    __threadfence();
}

// =====================================================================
// Fused kernel (occ=1): blocks [0,32) scan (private SMs), rest proj.
// Scan: windowed linearization, W=8 steps per barrier.
//   exact:  h_t = w_t + am·delta_t,  w = S-free trajectory,
//           delta_{k+1} = 0.9 delta_k + S_k  (scalar pair, per-thread)
//   approx: S_k = A_k + C·delta_k,  A_k = n·tanh(w_k) (reduced),
//           C = n·am·(1-tanh(w_0)^2) (one per window)
// 20 REDUX + 1 barrier per 8 timesteps.
// =====================================================================
__global__ __launch_bounds__(256, 1) void fused_kernel(const float* __restrict__ X,
                                                       const float* __restrict__ Iw,
                                                       const float* __restrict__ mw,
                                                       const float* __restrict__ nw,
                                                       float* __restrict__ out) {
    __shared__ float As[BK][BM + 4];
    __shared__ float Bs[BK][BN + 4];
    __shared__ int4  wsum[2][4][5];   // [parity][warp][5 int4 = 20 sums]

    const int bid = blockIdx.x;

    if (bid >= Bb) {
        // ================= PROJ TILE (unchanged) =================
        const int pbid = bid - Bb;
        const int tc   = pbid >> 7;
        const int rem  = pbid & 127;
        const int b    = rem >> 2;
        const int nc   = rem & 3;
        const long long m0 = (long long)b * Tt + (long long)tc * CHUNK;
        const int       n0 = nc * BN;

        const int tid = threadIdx.x;
        const int tx  = tid & 15;
        const int ty  = tid >> 4;

        unsigned long long acc[8][4];
#pragma unroll
        for (int i = 0; i < 8; i++)
#pragma unroll
            for (int j = 0; j < 4; j++) acc[i][j] = 0ull;

        for (int kt = 0; kt < DIN; kt += BK) {
#pragma unroll
            for (int q = 0; q < 4; q++) {
                int p   = tid + q * 256;
                int row = p >> 3;
                int kq  = p & 7;
                float4 av = *(const float4*)(X + (m0 + row) * DIN + kt + kq * 4);
                As[kq * 4 + 0][row] = av.x; As[kq * 4 + 1][row] = av.y;
                As[kq * 4 + 2][row] = av.z; As[kq * 4 + 3][row] = av.w;
                float4 bv = *(const float4*)(Iw + (long long)(n0 + row) * DIN + kt + kq * 4);
                Bs[kq * 4 + 0][row] = ALPHA_F * bv.x; Bs[kq * 4 + 1][row] = ALPHA_F * bv.y;
                Bs[kq * 4 + 2][row] = ALPHA_F * bv.z; Bs[kq * 4 + 3][row] = ALPHA_F * bv.w;
            }
            __syncthreads();

#pragma unroll
            for (int k = 0; k < BK; k++) {
                float4 a0 = *(const float4*)&As[k][ty * 8];
                float4 a1 = *(const float4*)&As[k][ty * 8 + 4];
                const unsigned long long* bp =
                    (const unsigned long long*)&Bs[k][tx * 8];
                unsigned long long pb0 = bp[0], pb1 = bp[1], pb2 = bp[2], pb3 = bp[3];
                float av[8] = {a0.x, a0.y, a0.z, a0.w, a1.x, a1.y, a1.z, a1.w};
#pragma unroll
                for (int i = 0; i < 8; i++) {
                    unsigned long long pa;
                    PACK2(pa, av[i], av[i]);
                    FMA2(acc[i][0], pa, pb0);
                    FMA2(acc[i][1], pa, pb1);
                    FMA2(acc[i][2], pa, pb2);
                    FMA2(acc[i][3], pa, pb3);
                }
            }
            __syncthreads();
        }

#pragma unroll
        for (int i = 0; i < 8; i++) {
            float4 o0, o1;
            UNPACK2(o0.x, o0.y, acc[i][0]);
            UNPACK2(o0.z, o0.w, acc[i][1]);
            UNPACK2(o1.x, o1.y, acc[i][2]);
            UNPACK2(o1.z, o1.w, acc[i][3]);
            long long row = m0 + ty * 8 + i;
            float* op = g_xproj + row * Hh + n0 + tx * 8;
            *(float4*)op       = o0;
            *(float4*)(op + 4) = o1;
        }

        __threadfence();
        __syncthreads();
        if (tid == 0) atomicAdd(&g_cnt[b][tc], 1);
        return;
    }

    // ================= SCAN =================
    if (threadIdx.x >= 128) return;

    const int b    = bid;
    const int tid  = threadIdx.x;
    const int wid  = tid >> 5;
    const int lane = tid & 31;
    const int i0   = tid * 4;

    // constants
    float am0[4], am1[4];                 // alpha*m * 2^-20 (h-update, delta-hat)
    float amr0[4], amr1[4];               // alpha*m (C partials)
    unsigned long long n01[4], n24[4];    // (n0,n1)*2^20 ; (n0,n1)*2^24
#pragma unroll
    for (int j = 0; j < 4; j++) {
        float m0v = mw[(i0 + j) * 2 + 0], m1v = mw[(i0 + j) * 2 + 1];
        float n0v = nw[(i0 + j) * 2 + 0], n1v = nw[(i0 + j) * 2 + 1];
        am0[j]  = (ALPHA_F * FXINV) * m0v;
        am1[j]  = (ALPHA_F * FXINV) * m1v;
        amr0[j] = ALPHA_F * m0v;
        amr1[j] = ALPHA_F * m1v;
        PACK2(n01[j], FXSCALE * n0v, FXSCALE * n1v);
        PACK2(n24[j], CSCALE * n0v, CSCALE * n1v);
    }

    const float4* xp4  = (const float4*)(g_xproj + (size_t)b * Tt * Hh);
    float*        outb = out + (size_t)b * Tt * Hh;

    // trajectory w[k][j], k=0..W (w[0] = h at window start, exact)
    float w[W + 1][4];
    float4 xpr[W];          // prefetched xp rows for NEXT window's trajectory

    // partials for one window: A_k=(n·tanh(w_k)) k=0..7 (packed pairs),
    // C at w_0; 20 REDUX; lane0 posts 5 int4.
    auto post_window = [&](int parity) {
        unsigned long long Ap[W];
#pragma unroll
        for (int k = 0; k < W; k++) Ap[k] = 0ull;
        unsigned long long Cp0 = 0ull, Cp1 = 0ull;
        float th0[4];
#pragma unroll
        for (int j = 0; j < 4; j++) {
            th0[j] = tanh_fast(w[0][j]);
            unsigned long long tp;
            PACK2(tp, th0[j], th0[j]);
            FMA2(Ap[0], tp, n01[j]);
        }
#pragma unroll
        for (int k = 1; k < W; k++) {
#pragma unroll
            for (int j = 0; j < 4; j++) {
                float th = tanh_fast(w[k][j]);
                unsigned long long tp;
                PACK2(tp, th, th);
                FMA2(Ap[k], tp, n01[j]);
            }
        }
#pragma unroll
        for (int j = 0; j < 4; j++) {
            float d  = fmaf(-th0[j], th0[j], 1.0f);
            float c0 = amr0[j] * d, c1 = amr1[j] * d;
            unsigned long long p0, p1;
            PACK2(p0, c0, c0);
            FMA2(Cp0, p0, n24[j]);               // (C00, C10)
            PACK2(p1, c1, c1);
            FMA2(Cp1, p1, n24[j]);               // (C01, C11)
        }
        unsigned q[20];
#pragma unroll
        for (int k = 0; k < W; k++) {
            float a0, a1;
            UNPACK2(a0, a1, Ap[k]);
            q[2 * k]     = __reduce_add_sync(0xffffffffu, __float_as_uint(a0 + MAGICF));
            q[2 * k + 1] = __reduce_add_sync(0xffffffffu, __float_as_uint(a1 + MAGICF));
        }
        {
            float c00, c10, c01, c11;
            UNPACK2(c00, c10, Cp0);
            UNPACK2(c01, c11, Cp1);
            q[16] = __reduce_add_sync(0xffffffffu, __float_as_uint(c00 + MAGICF));
            q[17] = __reduce_add_sync(0xffffffffu, __float_as_uint(c01 + MAGICF));
            q[18] = __reduce_add_sync(0xffffffffu, __float_as_uint(c10 + MAGICF));
            q[19] = __reduce_add_sync(0xffffffffu, __float_as_uint(c11 + MAGICF));
        }
        if (lane == 0) {
#pragma unroll
            for (int g = 0; g < 5; g++)
                wsum[parity][wid][g] = make_int4((int)q[4 * g], (int)q[4 * g + 1],
                                                 (int)q[4 * g + 2], (int)q[4 * g + 3]);
        }
    };

    // ---------------- prologue: window 0 ----------------
    wait_chunk(b, 0);
#pragma unroll
    for (int j = 0; j < 4; j++) w[0][j] = 0.f;    // h_0 = 0
#pragma unroll
    for (int k = 0; k < W; k++) xpr[k] = xp4[k * 128 + tid];
#pragma unroll
    for (int k = 0; k < W; k++) {
        w[k + 1][0] = fmaf(0.9f, w[k][0], xpr[k].x);
        w[k + 1][1] = fmaf(0.9f, w[k][1], xpr[k].y);
        w[k + 1][2] = fmaf(0.9f, w[k][2], xpr[k].z);
        w[k + 1][3] = fmaf(0.9f, w[k][3], xpr[k].w);
    }
    post_window(0);
    // prefetch rows for window 1 (8..15, still chunk 0)
#pragma unroll
    for (int k = 0; k < W; k++) xpr[k] = xp4[(W + k) * 128 + tid];
    __syncthreads();

    float* optr = outb + i0;

    // ---------------- main loop: W timesteps / iteration ----------------
    for (int i = 0; i < NW; i++) {
        const int p = i & 1;

        // combine this window's reductions (4 warps x 20 sums)
        float A0[W], A1[W], C00, C01, C10, C11;
        {
            unsigned s[20];
#pragma unroll
            for (int g = 0; g < 5; g++) {
                int4 x0 = wsum[p][0][g], x1 = wsum[p][1][g];
                int4 x2 = wsum[p][2][g], x3 = wsum[p][3][g];
                s[4 * g + 0] = (unsigned)(x0.x + x1.x + x2.x + x3.x) - BIAS_FIX;
                s[4 * g + 1] = (unsigned)(x0.y + x1.y + x2.y + x3.y) - BIAS_FIX;
                s[4 * g + 2] = (unsigned)(x0.z + x1.z + x2.z + x3.z) - BIAS_FIX;
                s[4 * g + 3] = (unsigned)(x0.w + x1.w + x2.w + x3.w) - BIAS_FIX;
            }
#pragma unroll
            for (int k = 0; k < W; k++) {
                A0[k] = __uint_as_float(s[2 * k]) - MAGICF;       // x2^20
                A1[k] = __uint_as_float(s[2 * k + 1]) - MAGICF;
            }
            C00 = fmaf(__uint_as_float(s[16]), CINV, MCC);
            C01 = fmaf(__uint_as_float(s[17]), CINV, MCC);
            C10 = fmaf(__uint_as_float(s[18]), CINV, MCC);
            C11 = fmaf(__uint_as_float(s[19]), CINV, MCC);
        }

        // scalar delta recurrence + outputs (delta resets each window)
        float d0 = 0.f, d1 = 0.f;
        float ho0, ho1, ho2, ho3;
#pragma unroll
        for (int k = 0; k < W; k++) {
            float S0 = fmaf(C00, d0, fmaf(C01, d1, A0[k]));
            float S1 = fmaf(C10, d0, fmaf(C11, d1, A1[k]));
            d0 = fmaf(0.9f, d0, S0);
            d1 = fmaf(0.9f, d1, S1);
            ho0 = fmaf(am0[0], d0, fmaf(am1[0], d1, w[k + 1][0]));
            ho1 = fmaf(am0[1], d0, fmaf(am1[1], d1, w[k + 1][1]));
            ho2 = fmaf(am0[2], d0, fmaf(am1[2], d1, w[k + 1][2]));
            ho3 = fmaf(am0[3], d0, fmaf(am1[3], d1, w[k + 1][3]));
            *(float4*)(optr + (size_t)k * Hh) = make_float4(ho0, ho1, ho2, ho3);
        }
        optr += (size_t)W * Hh;

        if (i + 1 < NW) {
            // next window's trajectory from exact H' = last output
            w[0][0] = ho0; w[0][1] = ho1; w[0][2] = ho2; w[0][3] = ho3;
#pragma unroll
            for (int k = 0; k < W; k++) {
                w[k + 1][0] = fmaf(0.9f, w[k][0], xpr[k].x);
                w[k + 1][1] = fmaf(0.9f, w[k][1], xpr[k].y);
                w[k + 1][2] = fmaf(0.9f, w[k][2], xpr[k].z);
                w[k + 1][3] = fmaf(0.9f, w[k][3], xpr[k].w);
            }
            // prefetch xp rows for window i+2 (overlaps REDUX tail + bar)
            {
                int r0 = (i + 2) * W;
                if (r0 < Tt && (r0 & (CHUNK - 1)) == 0) wait_chunk(b, r0 >> 7);
#pragma unroll
                for (int k = 0; k < W; k++) {
                    int rr = r0 + k;
                    if (rr >= Tt) rr = Tt - 1;
                    xpr[k] = xp4[(size_t)rr * 128 + tid];
                }
            }
            post_window(p ^ 1);
            __syncthreads();
        }
    }
}

// =====================================================================
extern "C" void kernel_launch(void* const* d_in, const int* in_sizes, int n_in,
                              void* d_out, int out_size) {
    const float* x  = (const float*)d_in[0];  // [32, 2048, 128]
    const float* m  = (const float*)d_in[1];  // [512, 2]
    const float* n  = (const float*)d_in[2];  // [512, 2]
    const float* Iw = (const float*)d_in[3];  // [512, 128]
    float* out = (float*)d_out;               // [32, 2048, 512]

    zero_cnt_kernel<<<1, 512>>>();
    fused_kernel<<<Bb + (Bb * NCH * 4), 256>>>(x, Iw, m, n, out);
}